// round 8
// baseline (speedup 1.0000x reference)
#include <cuda_runtime.h>
#include <cuda_fp16.h>
#include <math.h>

#define NX 128
#define NG 64
#define P  8192
#define T_STEPS 4
#define N_ITER 50
#define KAPPA 0.8f
#define LAMDA 0.9f
#define YITA  0.1f
#define NEG_SLOPE 0.01f

#define NBLK 128         // blocks; each owns 64 contiguous columns
#define CPB  64          // columns per block (64 cols * 2B = one 128B line/row)
#define NTHR 1024        // 32 warps/SM for MLP

// Device scratch (static __device__ — the sanctioned path)
__device__ __half g_M16[(size_t)P * P];   // 128 MB fp16 copy of M0
__device__ float g_hbuf[2][P];            // double-buffered h (by publish parity)
__device__ float g_dotbuf[2][3 * NBLK];   // double-buffered dot partials
__device__ float g_losspart[NBLK];
__device__ float g_u[3 * P];              // u_s = p+h from earlier timesteps
__device__ float g_v[3 * P];              // v_s = p-h
__device__ float g_loss;
__device__ volatile int g_flag[NBLK];     // publish counters (0 between launches)
__device__ volatile unsigned g_gen;       // end-of-kernel barrier generation
__device__ unsigned g_count;              // barrier arrivals (0 between barriers)

__device__ __forceinline__ float f_p(float v) {
    float c = fminf(fmaxf(v, -1.0f), 1.0f);
    return (c >= 0.0f) ? c : NEG_SLOPE * c;
}

// Classic atomic grid barrier — used ONCE at kernel end (for flag reset).
__device__ __forceinline__ void grid_barrier() {
    __syncthreads();
    if (threadIdx.x == 0) {
        unsigned my = g_gen;
        __threadfence();
        if (atomicAdd(&g_count, 1) == NBLK - 1) {
            g_count = 0;
            __threadfence();
            g_gen = my + 1;
        } else {
            while (g_gen == my) __nanosleep(64);
        }
    }
    __syncthreads();
}

// Convert M0 fp32 -> fp16 (runs each replay)
__global__ void k_convert(const float* __restrict__ M) {
    size_t i = ((size_t)blockIdx.x * blockDim.x + threadIdx.x) * 8;
    const float4* src = (const float4*)(M + i);
    float4 a = src[0];
    float4 b = src[1];
    __half2 h0 = __floats2half2_rn(a.x, a.y);
    __half2 h1 = __floats2half2_rn(a.z, a.w);
    __half2 h2 = __floats2half2_rn(b.x, b.y);
    __half2 h3 = __floats2half2_rn(b.z, b.w);
    uint4 out;
    out.x = *(unsigned*)&h0;
    out.y = *(unsigned*)&h1;
    out.z = *(unsigned*)&h2;
    out.w = *(unsigned*)&h3;
    *(uint4*)(g_M16 + i) = out;
}

// Persistent per-timestep kernel with fine-grained dataflow sync.
// Publish #m (m=1 init, m=it+2 end of iter it) writes g_hbuf[m&1]; input for
// iteration it is publish #it+1 -> buffer (it+1)&1. flag[b] = publishes done.
// Matvec chunk k consumes h rows [128k,128k+128) owned by blocks 2k,2k+1;
// waits are per-group (8 chunks) per-warp and pipeline into the M stream.
__global__ void __launch_bounds__(NTHR, 1)
k_attractor(const float* __restrict__ x, const float* __restrict__ gin,
            float* __restrict__ out, int t,
            float lam_pow, float w0, float w1, float w2) {
    __shared__ float red[CPB][33];     // red[col][warp] partials, padded
    __shared__ float red2[CPB];
    __shared__ float dsum[3][4];
    __shared__ float psm[3][2];

    const int b    = blockIdx.x;
    const int tid  = threadIdx.x;
    const int lane = tid & 31;
    const int wid  = tid >> 5;         // 0..31
    const int rg   = tid >> 3;         // row group 0..127
    const int cc   = tid & 7;          // col chunk 0..7
    const int w4   = wid << 2;         // warp's base rg
    const int cb0  = b * CPB;
    const int nterms = t;

    // ---- init publish (#1): h0 slice + dot partials ----
    float hn_val = 0.f;                // this thread's owned column value (tid<64)
    if (tid < CPB) {
        int col = cb0 + tid;
        hn_val = f_p(gin[t * NG + (col & (NG - 1))]);
        g_hbuf[1][col] = hn_val;
        for (int s = 0; s < nterms; ++s) {
            float wv = hn_val * __ldg(&g_u[s * P + col]);
#pragma unroll
            for (int off = 16; off; off >>= 1)
                wv += __shfl_xor_sync(0xFFFFFFFFu, wv, off);
            if (lane == 0) psm[s][wid] = wv;
        }
        __threadfence();
    }
    __syncthreads();
    if (tid == 0) {
        for (int s = 0; s < nterms; ++s)
            g_dotbuf[1][s * NBLK + b] = psm[s][0] + psm[s][1];
        __threadfence();
        g_flag[b] = 1;
    }

    for (int it = 0; it < N_ITER; ++it) {
        const float* __restrict__ hin = g_hbuf[(it + 1) & 1];
        const int target = it + 1;

        const uint4* __restrict__ Mp =
            (const uint4*)(g_M16 + (size_t)rg * P + cb0 + cc * 8);
        float a0=0.f,a1=0.f,a2=0.f,a3=0.f,a4=0.f,a5=0.f,a6=0.f,a7=0.f;

        for (int grp = 0; grp < 8; ++grp) {
            // wait: publishes of blocks owning rows [grp*1024, grp*1024+1024)
            if (lane < 16) {
                while (g_flag[grp * 16 + lane] < target) __nanosleep(32);
            }
            __syncwarp();
            __threadfence();           // acquire: order h reads after flag
#pragma unroll
            for (int k2 = 0; k2 < 8; ++k2) {
                int k = grp * 8 + k2;
                float v = 0.f;
                if (lane < 4) v = __ldcg(&hin[128 * k + w4 + lane]);
                float hv = __shfl_sync(0xFFFFFFFFu, v, lane >> 3);
                uint4 m = __ldg(Mp);
                Mp += (128 * P) / 8;   // next 128-row step (uint4 stride)
                float2 f0 = __half22float2(*(__half2*)&m.x);
                float2 f1 = __half22float2(*(__half2*)&m.y);
                float2 f2 = __half22float2(*(__half2*)&m.z);
                float2 f3 = __half22float2(*(__half2*)&m.w);
                a0 = fmaf(hv, f0.x, a0); a1 = fmaf(hv, f0.y, a1);
                a2 = fmaf(hv, f1.x, a2); a3 = fmaf(hv, f1.y, a3);
                a4 = fmaf(hv, f2.x, a4); a5 = fmaf(hv, f2.y, a5);
                a6 = fmaf(hv, f3.x, a6); a7 = fmaf(hv, f3.y, a7);
            }
        }
        // warp reduce across the 4 rg values in this warp (fixed xor order)
#pragma unroll
        for (int off = 8; off < 32; off <<= 1) {
            a0 += __shfl_xor_sync(0xFFFFFFFFu, a0, off);
            a1 += __shfl_xor_sync(0xFFFFFFFFu, a1, off);
            a2 += __shfl_xor_sync(0xFFFFFFFFu, a2, off);
            a3 += __shfl_xor_sync(0xFFFFFFFFu, a3, off);
            a4 += __shfl_xor_sync(0xFFFFFFFFu, a4, off);
            a5 += __shfl_xor_sync(0xFFFFFFFFu, a5, off);
            a6 += __shfl_xor_sync(0xFFFFFFFFu, a6, off);
            a7 += __shfl_xor_sync(0xFFFFFFFFu, a7, off);
        }
        if (lane < 8) {
            int c0 = lane * 8;
            red[c0 + 0][wid] = a0; red[c0 + 1][wid] = a1;
            red[c0 + 2][wid] = a2; red[c0 + 3][wid] = a3;
            red[c0 + 4][wid] = a4; red[c0 + 5][wid] = a5;
            red[c0 + 6][wid] = a6; red[c0 + 7][wid] = a7;
        }
        __syncthreads();

        // ---- parallel column reduce (512 thr) + dots (128 thr, disjoint) ----
        if (tid < 512) {
            int c = tid >> 3, j = tid & 7;
            float s = ((red[c][j * 4] + red[c][j * 4 + 1]) +
                       (red[c][j * 4 + 2] + red[c][j * 4 + 3]));
            s += __shfl_xor_sync(0xFFFFFFFFu, s, 1);
            s += __shfl_xor_sync(0xFFFFFFFFu, s, 2);
            s += __shfl_xor_sync(0xFFFFFFFFu, s, 4);
            if (j == 0) red2[c] = s;
        } else if (tid >= 512 && tid < 512 + NBLK) {
            // dots: all flags >= target observed during matvec -> dotbuf ready
            int i = tid - 512;
            for (int s = 0; s < nterms; ++s) {
                float a = __ldcg(&g_dotbuf[(it + 1) & 1][s * NBLK + i]);
#pragma unroll
                for (int off = 16; off; off >>= 1)
                    a += __shfl_xor_sync(0xFFFFFFFFu, a, off);
                if (lane == 0) dsum[s][(tid - 512) >> 5] = a;
            }
        }
        __syncthreads();

        // ---- rank-1 corrections + pointwise update + publish ----
        if (tid < CPB) {
            int col = cb0 + tid;
            float y = red2[tid] * lam_pow;
            if (nterms > 0) {
                float d0 = ((dsum[0][0] + dsum[0][1]) + dsum[0][2]) + dsum[0][3];
                y = fmaf(w0 * d0, __ldg(&g_v[0 * P + col]), y);
            }
            if (nterms > 1) {
                float d1 = ((dsum[1][0] + dsum[1][1]) + dsum[1][2]) + dsum[1][3];
                y = fmaf(w1 * d1, __ldg(&g_v[1 * P + col]), y);
            }
            if (nterms > 2) {
                float d2 = ((dsum[2][0] + dsum[2][1]) + dsum[2][2]) + dsum[2][3];
                y = fmaf(w2 * d2, __ldg(&g_v[2 * P + col]), y);
            }
            float ho = hn_val;
            hn_val = f_p(KAPPA * ho + ho * y);
            if (it < N_ITER - 1) {
                g_hbuf[it & 1][col] = hn_val;   // publish #it+2 -> buf[it&1]
                for (int s = 0; s < nterms; ++s) {
                    float wv = hn_val * __ldg(&g_u[s * P + col]);
#pragma unroll
                    for (int off = 16; off; off >>= 1)
                        wv += __shfl_xor_sync(0xFFFFFFFFu, wv, off);
                    if (lane == 0) psm[s][wid] = wv;
                }
                __threadfence();
            }
        }
        if (it < N_ITER - 1) {
            __syncthreads();
            if (tid == 0) {
                for (int s = 0; s < nterms; ++s)
                    g_dotbuf[it & 1][s * NBLK + b] = psm[s][0] + psm[s][1];
                __threadfence();
                g_flag[b] = it + 2;
            }
        }
    }

    // ---- epilogue: loss partial, u/v store, block 0 finalizes ----
    if (tid < CPB) {
        int col = cb0 + tid;
        float p = x[t * NX + (col >> 6)] * gin[t * NG + (col & (NG - 1))];
        if (t < 3) {
            g_u[t * P + col] = p + hn_val;
            g_v[t * P + col] = p - hn_val;
        }
        float a = fabsf(p - hn_val);
#pragma unroll
        for (int off = 16; off; off >>= 1)
            a += __shfl_xor_sync(0xFFFFFFFFu, a, off);
        if (lane == 0) psm[0][wid] = a;
        __threadfence();
    }
    __syncthreads();
    if (tid == 0) {
        g_losspart[b] = psm[0][0] + psm[0][1];
        __threadfence();
        g_flag[b] = N_ITER + 1;
    }

    if (b == 0) {
        if (tid < NBLK) {
            while (g_flag[tid] < N_ITER + 1) __nanosleep(32);
        }
        __syncthreads();
        __threadfence();
        if (tid < NBLK) {
            float a = __ldcg(&g_losspart[tid]);
#pragma unroll
            for (int off = 16; off; off >>= 1)
                a += __shfl_xor_sync(0xFFFFFFFFu, a, off);
            if (lane == 0) dsum[0][wid] = a;
        }
        __syncthreads();
        if (tid == 0) {
            float L = (t == 0 ? 0.f : g_loss) +
                      (((dsum[0][0] + dsum[0][1]) + dsum[0][2]) + dsum[0][3]);
            g_loss = L;
            *out = L;
        }
    }

    // safe flag reset behind a true barrier (next launch starts from 0)
    grid_barrier();
    if (tid == 0) g_flag[b] = 0;
}

extern "C" void kernel_launch(void* const* d_in, const int* in_sizes, int n_in,
                              void* d_out, int out_size) {
    const float* x = (const float*)d_in[0];   // [4,128]
    const float* g = (const float*)d_in[1];   // [4,64]
    const float* M = (const float*)d_in[2];   // [8192,8192]
    float* out = (float*)d_out;
    (void)in_sizes; (void)n_in; (void)out_size;

    k_convert<<<(int)((size_t)P * P / 8 / 256), 256>>>(M);

    for (int t = 0; t < T_STEPS; ++t) {
        float lam_pow = 1.0f;
        for (int i = 0; i < t; ++i) lam_pow *= LAMDA;
        float w[3] = {0.0f, 0.0f, 0.0f};
        for (int s = 0; s < t; ++s) {
            float lp = 1.0f;
            for (int i = 0; i < t - 1 - s; ++i) lp *= LAMDA;
            w[s] = YITA * lp;
        }
        k_attractor<<<NBLK, NTHR>>>(x, g, out, t, lam_pow, w[0], w[1], w[2]);
    }
}

// round 10
// speedup vs baseline: 1.7318x; 1.7318x over previous
#include <cuda_runtime.h>
#include <cuda_fp16.h>
#include <math.h>

#define NX 128
#define NG 64
#define P  8192
#define T_STEPS 4
#define N_ITER 50
#define KAPPA 0.8f
#define LAMDA 0.9f
#define YITA  0.1f
#define NEG_SLOPE 0.01f

#define NBLK 128         // blocks; each owns 64 contiguous columns
#define CPB  64          // columns per block (64 cols * 2B = one 128B line/row)
#define NTHR 1024        // 32 warps/SM for MLP

// Device scratch (static __device__ — the sanctioned path)
__device__ __half g_M16[(size_t)P * P];   // 128 MB fp16 copy of M0
__device__ float g_h[P];
__device__ float g_u[3 * P];              // u_s = p+h from earlier timesteps
__device__ float g_v[3 * P];              // v_s = p-h
__device__ float g_dotpart[3 * NBLK];     // per-block partials (dots / loss)
__device__ float g_loss;
__device__ volatile unsigned g_gen;       // grid barrier generation
__device__ unsigned g_count;              // barrier arrivals (0 between barriers)

__device__ __forceinline__ float f_p(float v) {
    float c = fminf(fmaxf(v, -1.0f), 1.0f);
    return (c >= 0.0f) ? c : NEG_SLOPE * c;
}

// L2 access policies (createpolicy + cache_hint form: valid for v4.b32).
__device__ __forceinline__ unsigned long long make_policy_keep() {
    unsigned long long pol;
    asm("createpolicy.fractional.L2::evict_last.b64 %0, 1.0;" : "=l"(pol));
    return pol;
}
__device__ __forceinline__ unsigned long long make_policy_stream() {
    unsigned long long pol;
    asm("createpolicy.fractional.L2::evict_first.b64 %0, 1.0;" : "=l"(pol));
    return pol;
}
__device__ __forceinline__ uint4 ldg_hint(const uint4* p, unsigned long long pol) {
    uint4 r;
    asm("ld.global.nc.L2::cache_hint.v4.b32 {%0,%1,%2,%3}, [%4], %5;"
        : "=r"(r.x), "=r"(r.y), "=r"(r.z), "=r"(r.w) : "l"(p), "l"(pol));
    return r;
}

// Software grid barrier; all NBLK blocks co-resident (128 <= 148 SMs, 1/SM).
__device__ __forceinline__ void grid_barrier() {
    if (threadIdx.x < CPB) __threadfence();   // only tid<64 write globals
    __syncthreads();
    if (threadIdx.x == 0) {
        unsigned my = g_gen;
        if (atomicAdd(&g_count, 1) == NBLK - 1) {
            g_count = 0;
            __threadfence();
            g_gen = my + 1;   // release
        } else {
            while (g_gen == my) __nanosleep(64);
        }
    }
    __syncthreads();
    __threadfence();
}

// Convert M0 fp32 -> fp16 (runs each replay)
__global__ void k_convert(const float* __restrict__ M) {
    size_t i = ((size_t)blockIdx.x * blockDim.x + threadIdx.x) * 8;
    const float4* src = (const float4*)(M + i);
    float4 a = src[0];
    float4 b = src[1];
    __half2 h0 = __floats2half2_rn(a.x, a.y);
    __half2 h1 = __floats2half2_rn(a.z, a.w);
    __half2 h2 = __floats2half2_rn(b.x, b.y);
    __half2 h3 = __floats2half2_rn(b.z, b.w);
    uint4 out;
    out.x = *(unsigned*)&h0;
    out.y = *(unsigned*)&h1;
    out.z = *(unsigned*)&h2;
    out.w = *(unsigned*)&h3;
    *(uint4*)(g_M16 + i) = out;
}

// Persistent per-timestep kernel: init + 50 attractor iterations + loss.
// M_t = lam_pow*M0 + sum_s w_s * outer(u_s, v_s), applied analytically.
// Block b owns columns [b*64, b*64+64); full h staged in smem each iter.
// M chunks k%4 != 3 loaded with evict_last policy (pin ~96 MB in 126 MB L2),
// k%4 == 3 with evict_first (stream 32 MB/iter from DRAM) -> most of the
// 128 MB/iter stream served at LTS rate instead of DRAM rate.
__global__ void __launch_bounds__(NTHR, 1)
k_attractor(const float* __restrict__ x, const float* __restrict__ gin,
            float* __restrict__ out, int t,
            float lam_pow, float w0, float w1, float w2) {
    __shared__ float h_sm[P];          // 32 KB full h
    __shared__ float red[CPB][33];     // red[col][warp] partials, padded
    __shared__ float red2[CPB];
    __shared__ float dsum[3][4];       // dot reduce: 4 warp sums per term
    __shared__ float psm[3][2];        // publish reduce: 2 warp sums per term

    const int b    = blockIdx.x;
    const int tid  = threadIdx.x;
    const int lane = tid & 31;
    const int wid  = tid >> 5;         // 0..31
    const int rg   = tid >> 3;         // row group 0..127
    const int cc   = tid & 7;          // col chunk 0..7
    const int cb0  = b * CPB;
    const int nterms = t;

    const unsigned long long polK = make_policy_keep();
    const unsigned long long polS = make_policy_stream();

    const uint4* __restrict__ Mbase4 =
        (const uint4*)(g_M16 + (size_t)rg * P + cb0 + cc * 8);
    const size_t CSTRIDE = (size_t)(128 * P) / 8;   // uint4 per 128-row chunk

    // ---- init: h0 = f_p(tile(g_t)) computed locally (no global traffic) ----
    for (int k = tid; k < P; k += NTHR)
        h_sm[k] = f_p(gin[t * NG + (k & (NG - 1))]);
    __syncthreads();

    // ---- prologue: publish dot partials of h0 (only t>0) ----
    if (nterms > 0) {
        if (tid < CPB) {
            int col = cb0 + tid;
            float hv = h_sm[col];
            for (int s = 0; s < nterms; ++s) {
                float w = hv * __ldg(&g_u[s * P + col]);
#pragma unroll
                for (int off = 16; off; off >>= 1)
                    w += __shfl_xor_sync(0xFFFFFFFFu, w, off);
                if (lane == 0) psm[s][wid] = w;
            }
        }
        __syncthreads();
        if (tid == 0)
            for (int s = 0; s < nterms; ++s)
                g_dotpart[s * NBLK + b] = psm[s][0] + psm[s][1];
        grid_barrier();
    }

    float hn_val = 0.f;   // tid<64: this thread's column value of h

    for (int it = 0; it < N_ITER; ++it) {
        // ---- global dots: identical fixed-order value in every block ----
        if (nterms > 0 && tid < NBLK) {
            for (int s = 0; s < nterms; ++s) {
                float a = __ldcg(&g_dotpart[s * NBLK + tid]);
#pragma unroll
                for (int off = 16; off; off >>= 1)
                    a += __shfl_xor_sync(0xFFFFFFFFu, a, off);
                if (lane == 0) dsum[s][wid] = a;
            }
        }

        // ---- refresh full h (it==0: already computed locally) ----
        if (it > 0) {
            for (int i = tid; i < P / 4; i += NTHR)
                ((float4*)h_sm)[i] = __ldcg(((const float4*)g_h) + i);
        }
        __syncthreads();

        float dots[3] = {0.f, 0.f, 0.f};
        for (int s = 0; s < nterms; ++s)
            dots[s] = ((dsum[s][0] + dsum[s][1]) + dsum[s][2]) + dsum[s][3];

        // ---- matvec: 64 rows/thread; 3-of-4 chunks L2-pinned, 1-of-4 stream ----
        const uint4* Mp = Mbase4;
        float a0=0.f,a1=0.f,a2=0.f,a3=0.f,a4=0.f,a5=0.f,a6=0.f,a7=0.f;
#pragma unroll 4
        for (int kk = 0; kk < P / 512; ++kk) {         // 16 groups of 4 chunks
#pragma unroll
            for (int j = 0; j < 4; ++j) {
                uint4 m = ldg_hint(Mp, (j == 3) ? polS : polK);
                Mp += CSTRIDE;
                float hv = h_sm[rg + 128 * (kk * 4 + j)];
                float2 f0 = __half22float2(*(__half2*)&m.x);
                float2 f1 = __half22float2(*(__half2*)&m.y);
                float2 f2 = __half22float2(*(__half2*)&m.z);
                float2 f3 = __half22float2(*(__half2*)&m.w);
                a0 = fmaf(hv, f0.x, a0); a1 = fmaf(hv, f0.y, a1);
                a2 = fmaf(hv, f1.x, a2); a3 = fmaf(hv, f1.y, a3);
                a4 = fmaf(hv, f2.x, a4); a5 = fmaf(hv, f2.y, a5);
                a6 = fmaf(hv, f3.x, a6); a7 = fmaf(hv, f3.y, a7);
            }
        }
        // warp reduce across the 4 rg values in this warp (fixed xor order)
#pragma unroll
        for (int off = 8; off < 32; off <<= 1) {
            a0 += __shfl_xor_sync(0xFFFFFFFFu, a0, off);
            a1 += __shfl_xor_sync(0xFFFFFFFFu, a1, off);
            a2 += __shfl_xor_sync(0xFFFFFFFFu, a2, off);
            a3 += __shfl_xor_sync(0xFFFFFFFFu, a3, off);
            a4 += __shfl_xor_sync(0xFFFFFFFFu, a4, off);
            a5 += __shfl_xor_sync(0xFFFFFFFFu, a5, off);
            a6 += __shfl_xor_sync(0xFFFFFFFFu, a6, off);
            a7 += __shfl_xor_sync(0xFFFFFFFFu, a7, off);
        }
        if (lane < 8) {
            int c0 = lane * 8;
            red[c0 + 0][wid] = a0; red[c0 + 1][wid] = a1;
            red[c0 + 2][wid] = a2; red[c0 + 3][wid] = a3;
            red[c0 + 4][wid] = a4; red[c0 + 5][wid] = a5;
            red[c0 + 6][wid] = a6; red[c0 + 7][wid] = a7;
        }
        __syncthreads();

        // ---- parallel column reduce: 512 threads, 8 per column ----
        if (tid < 512) {
            int c = tid >> 3, j = tid & 7;
            float s = ((red[c][j * 4] + red[c][j * 4 + 1]) +
                       (red[c][j * 4 + 2] + red[c][j * 4 + 3]));
            s += __shfl_xor_sync(0xFFFFFFFFu, s, 1);
            s += __shfl_xor_sync(0xFFFFFFFFu, s, 2);
            s += __shfl_xor_sync(0xFFFFFFFFu, s, 4);
            if (j == 0) red2[c] = s;
        }
        __syncthreads();

        // ---- rank-1 corrections + pointwise update ----
        if (tid < CPB) {
            int col = cb0 + tid;
            float y = red2[tid] * lam_pow;
            if (nterms > 0) y = fmaf(w0 * dots[0], __ldg(&g_v[0 * P + col]), y);
            if (nterms > 1) y = fmaf(w1 * dots[1], __ldg(&g_v[1 * P + col]), y);
            if (nterms > 2) y = fmaf(w2 * dots[2], __ldg(&g_v[2 * P + col]), y);
            float ho = h_sm[col];
            hn_val = f_p(KAPPA * ho + ho * y);
            g_h[col] = hn_val;
            // publish dot partials of new h (skip after last iteration)
            if (nterms > 0 && it < N_ITER - 1) {
                for (int s = 0; s < nterms; ++s) {
                    float w = hn_val * __ldg(&g_u[s * P + col]);
#pragma unroll
                    for (int off = 16; off; off >>= 1)
                        w += __shfl_xor_sync(0xFFFFFFFFu, w, off);
                    if (lane == 0) psm[s][wid] = w;
                }
            }
        }
        if (nterms > 0 && it < N_ITER - 1) {
            __syncthreads();
            if (tid == 0)
                for (int s = 0; s < nterms; ++s)
                    g_dotpart[s * NBLK + b] = psm[s][0] + psm[s][1];
        }
        grid_barrier();
    }

    // ---- epilogue: loss partial, store u/v, block 0 finalizes ----
    if (tid < CPB) {
        int col = cb0 + tid;
        float p = x[t * NX + (col >> 6)] * gin[t * NG + (col & (NG - 1))];
        float h = hn_val;
        if (t < 3) {
            g_u[t * P + col] = p + h;
            g_v[t * P + col] = p - h;
        }
        float a = fabsf(p - h);
#pragma unroll
        for (int off = 16; off; off >>= 1)
            a += __shfl_xor_sync(0xFFFFFFFFu, a, off);
        if (lane == 0) psm[0][wid] = a;
    }
    __syncthreads();
    if (tid == 0) g_dotpart[b] = psm[0][0] + psm[0][1];
    grid_barrier();

    if (b == 0) {
        if (tid < NBLK) {
            float a = __ldcg(&g_dotpart[tid]);
#pragma unroll
            for (int off = 16; off; off >>= 1)
                a += __shfl_xor_sync(0xFFFFFFFFu, a, off);
            if (lane == 0) dsum[0][wid] = a;
        }
        __syncthreads();
        if (tid == 0) {
            float L = (t == 0 ? 0.f : g_loss) +
                      (((dsum[0][0] + dsum[0][1]) + dsum[0][2]) + dsum[0][3]);
            g_loss = L;
            *out = L;
        }
    }
}

extern "C" void kernel_launch(void* const* d_in, const int* in_sizes, int n_in,
                              void* d_out, int out_size) {
    const float* x = (const float*)d_in[0];   // [4,128]
    const float* g = (const float*)d_in[1];   // [4,64]
    const float* M = (const float*)d_in[2];   // [8192,8192]
    float* out = (float*)d_out;
    (void)in_sizes; (void)n_in; (void)out_size;

    k_convert<<<(int)((size_t)P * P / 8 / 256), 256>>>(M);

    for (int t = 0; t < T_STEPS; ++t) {
        float lam_pow = 1.0f;
        for (int i = 0; i < t; ++i) lam_pow *= LAMDA;
        float w[3] = {0.0f, 0.0f, 0.0f};
        for (int s = 0; s < t; ++s) {
            float lp = 1.0f;
            for (int i = 0; i < t - 1 - s; ++i) lp *= LAMDA;
            w[s] = YITA * lp;
        }
        k_attractor<<<NBLK, NTHR>>>(x, g, out, t, lam_pow, w[0], w[1], w[2]);
    }
}

// round 11
// speedup vs baseline: 1.8066x; 1.0432x over previous
#include <cuda_runtime.h>
#include <cuda_fp16.h>
#include <math.h>

#define NX 128
#define NG 64
#define P  8192
#define T_STEPS 4
#define N_ITER 50
#define KAPPA 0.8f
#define LAMDA 0.9f
#define YITA  0.1f
#define NEG_SLOPE 0.01f

#define NBLK 128         // blocks; each owns 64 contiguous columns
#define CPB  64          // columns per block (64 cols * 2B = one 128B line/row)
#define NTHR 1024        // 32 warps/SM for MLP

// Device scratch (static __device__ — the sanctioned path)
__device__ __half g_M16[(size_t)P * P];   // 128 MB fp16 copy of M0
__device__ float g_h[P];
__device__ float g_u[3 * P];              // u_s = p+h from earlier timesteps
__device__ float g_v[3 * P];              // v_s = p-h
__device__ float g_dotpart[3 * NBLK];     // per-block partials (dots / loss)
__device__ float g_loss;
__device__ volatile unsigned g_gen;       // grid barrier generation
__device__ unsigned g_count;              // barrier arrivals (0 between barriers)

__device__ __forceinline__ float f_p(float v) {
    float c = fminf(fmaxf(v, -1.0f), 1.0f);
    return (c >= 0.0f) ? c : NEG_SLOPE * c;
}

// L2 access policies (createpolicy + cache_hint form: valid for v4.b32).
__device__ __forceinline__ unsigned long long make_policy_keep() {
    unsigned long long pol;
    asm("createpolicy.fractional.L2::evict_last.b64 %0, 1.0;" : "=l"(pol));
    return pol;
}
__device__ __forceinline__ unsigned long long make_policy_stream() {
    unsigned long long pol;
    asm("createpolicy.fractional.L2::evict_first.b64 %0, 1.0;" : "=l"(pol));
    return pol;
}
__device__ __forceinline__ uint4 ldg_hint(const uint4* p, unsigned long long pol) {
    uint4 r;
    asm("ld.global.nc.L2::cache_hint.v4.b32 {%0,%1,%2,%3}, [%4], %5;"
        : "=r"(r.x), "=r"(r.y), "=r"(r.z), "=r"(r.w) : "l"(p), "l"(pol));
    return r;
}

// Software grid barrier; all NBLK blocks co-resident (128 <= 148 SMs, 1/SM).
__device__ __forceinline__ void grid_barrier() {
    if (threadIdx.x < CPB) __threadfence();   // only tid<64 write globals
    __syncthreads();
    if (threadIdx.x == 0) {
        unsigned my = g_gen;
        if (atomicAdd(&g_count, 1) == NBLK - 1) {
            g_count = 0;
            __threadfence();
            g_gen = my + 1;   // release
        } else {
            while (g_gen == my) __nanosleep(64);
        }
    }
    __syncthreads();
    __threadfence();
}

// Convert M0 fp32 -> fp16 (runs each replay)
__global__ void k_convert(const float* __restrict__ M) {
    size_t i = ((size_t)blockIdx.x * blockDim.x + threadIdx.x) * 8;
    const float4* src = (const float4*)(M + i);
    float4 a = src[0];
    float4 b = src[1];
    __half2 h0 = __floats2half2_rn(a.x, a.y);
    __half2 h1 = __floats2half2_rn(a.z, a.w);
    __half2 h2 = __floats2half2_rn(b.x, b.y);
    __half2 h3 = __floats2half2_rn(b.z, b.w);
    uint4 out;
    out.x = *(unsigned*)&h0;
    out.y = *(unsigned*)&h1;
    out.z = *(unsigned*)&h2;
    out.w = *(unsigned*)&h3;
    *(uint4*)(g_M16 + i) = out;
}

// Persistent per-timestep kernel: init + 50 attractor iterations + loss.
// M_t = lam_pow*M0 + sum_s w_s * outer(u_s, v_s), applied analytically.
// Block b owns columns [b*64, b*64+64); full h staged in smem each iter.
// M chunks k%2 == 0 loaded with evict_last (pin 64 MB = 51% of L2 -> set
// overflow negligible, pin actually holds), k%2 == 1 with evict_first
// (stream 64 MB/iter from DRAM, overlapped). Stream floor ~= LTS cap.
__global__ void __launch_bounds__(NTHR, 1)
k_attractor(const float* __restrict__ x, const float* __restrict__ gin,
            float* __restrict__ out, int t,
            float lam_pow, float w0, float w1, float w2) {
    __shared__ float h_sm[P];          // 32 KB full h
    __shared__ float red[CPB][33];     // red[col][warp] partials, padded
    __shared__ float red2[CPB];
    __shared__ float dsum[3][4];       // dot reduce: 4 warp sums per term
    __shared__ float psm[3][2];        // publish reduce: 2 warp sums per term

    const int b    = blockIdx.x;
    const int tid  = threadIdx.x;
    const int lane = tid & 31;
    const int wid  = tid >> 5;         // 0..31
    const int rg   = tid >> 3;         // row group 0..127
    const int cc   = tid & 7;          // col chunk 0..7
    const int cb0  = b * CPB;
    const int nterms = t;

    const unsigned long long polK = make_policy_keep();
    const unsigned long long polS = make_policy_stream();

    const uint4* __restrict__ Mbase4 =
        (const uint4*)(g_M16 + (size_t)rg * P + cb0 + cc * 8);
    const size_t CSTRIDE = (size_t)(128 * P) / 8;   // uint4 per 128-row chunk

    // ---- init: h0 = f_p(tile(g_t)) computed locally (no global traffic) ----
    for (int k = tid; k < P; k += NTHR)
        h_sm[k] = f_p(gin[t * NG + (k & (NG - 1))]);
    __syncthreads();

    // ---- prologue: publish dot partials of h0 (only t>0) ----
    if (nterms > 0) {
        if (tid < CPB) {
            int col = cb0 + tid;
            float hv = h_sm[col];
            for (int s = 0; s < nterms; ++s) {
                float w = hv * __ldg(&g_u[s * P + col]);
#pragma unroll
                for (int off = 16; off; off >>= 1)
                    w += __shfl_xor_sync(0xFFFFFFFFu, w, off);
                if (lane == 0) psm[s][wid] = w;
            }
        }
        __syncthreads();
        if (tid == 0)
            for (int s = 0; s < nterms; ++s)
                g_dotpart[s * NBLK + b] = psm[s][0] + psm[s][1];
        grid_barrier();
    }

    float hn_val = 0.f;   // tid<64: this thread's column value of h

    for (int it = 0; it < N_ITER; ++it) {
        // ---- global dots: identical fixed-order value in every block ----
        if (nterms > 0 && tid < NBLK) {
            for (int s = 0; s < nterms; ++s) {
                float a = __ldcg(&g_dotpart[s * NBLK + tid]);
#pragma unroll
                for (int off = 16; off; off >>= 1)
                    a += __shfl_xor_sync(0xFFFFFFFFu, a, off);
                if (lane == 0) dsum[s][wid] = a;
            }
        }

        // ---- refresh full h (it==0: already computed locally) ----
        if (it > 0) {
            for (int i = tid; i < P / 4; i += NTHR)
                ((float4*)h_sm)[i] = __ldcg(((const float4*)g_h) + i);
        }
        __syncthreads();

        float dots[3] = {0.f, 0.f, 0.f};
        for (int s = 0; s < nterms; ++s)
            dots[s] = ((dsum[s][0] + dsum[s][1]) + dsum[s][2]) + dsum[s][3];

        // ---- matvec: 64 rows/thread; alternate chunks pinned/streamed ----
        const uint4* Mp = Mbase4;
        float a0=0.f,a1=0.f,a2=0.f,a3=0.f,a4=0.f,a5=0.f,a6=0.f,a7=0.f;
#pragma unroll 4
        for (int kk = 0; kk < P / 256; ++kk) {         // 32 groups of 2 chunks
#pragma unroll
            for (int j = 0; j < 2; ++j) {
                uint4 m = ldg_hint(Mp, j ? polS : polK);
                Mp += CSTRIDE;
                float hv = h_sm[rg + 128 * (kk * 2 + j)];
                float2 f0 = __half22float2(*(__half2*)&m.x);
                float2 f1 = __half22float2(*(__half2*)&m.y);
                float2 f2 = __half22float2(*(__half2*)&m.z);
                float2 f3 = __half22float2(*(__half2*)&m.w);
                a0 = fmaf(hv, f0.x, a0); a1 = fmaf(hv, f0.y, a1);
                a2 = fmaf(hv, f1.x, a2); a3 = fmaf(hv, f1.y, a3);
                a4 = fmaf(hv, f2.x, a4); a5 = fmaf(hv, f2.y, a5);
                a6 = fmaf(hv, f3.x, a6); a7 = fmaf(hv, f3.y, a7);
            }
        }
        // warp reduce across the 4 rg values in this warp (fixed xor order)
#pragma unroll
        for (int off = 8; off < 32; off <<= 1) {
            a0 += __shfl_xor_sync(0xFFFFFFFFu, a0, off);
            a1 += __shfl_xor_sync(0xFFFFFFFFu, a1, off);
            a2 += __shfl_xor_sync(0xFFFFFFFFu, a2, off);
            a3 += __shfl_xor_sync(0xFFFFFFFFu, a3, off);
            a4 += __shfl_xor_sync(0xFFFFFFFFu, a4, off);
            a5 += __shfl_xor_sync(0xFFFFFFFFu, a5, off);
            a6 += __shfl_xor_sync(0xFFFFFFFFu, a6, off);
            a7 += __shfl_xor_sync(0xFFFFFFFFu, a7, off);
        }
        if (lane < 8) {
            int c0 = lane * 8;
            red[c0 + 0][wid] = a0; red[c0 + 1][wid] = a1;
            red[c0 + 2][wid] = a2; red[c0 + 3][wid] = a3;
            red[c0 + 4][wid] = a4; red[c0 + 5][wid] = a5;
            red[c0 + 6][wid] = a6; red[c0 + 7][wid] = a7;
        }
        __syncthreads();

        // ---- parallel column reduce: 512 threads, 8 per column ----
        if (tid < 512) {
            int c = tid >> 3, j = tid & 7;
            float s = ((red[c][j * 4] + red[c][j * 4 + 1]) +
                       (red[c][j * 4 + 2] + red[c][j * 4 + 3]));
            s += __shfl_xor_sync(0xFFFFFFFFu, s, 1);
            s += __shfl_xor_sync(0xFFFFFFFFu, s, 2);
            s += __shfl_xor_sync(0xFFFFFFFFu, s, 4);
            if (j == 0) red2[c] = s;
        }
        __syncthreads();

        // ---- rank-1 corrections + pointwise update ----
        if (tid < CPB) {
            int col = cb0 + tid;
            float y = red2[tid] * lam_pow;
            if (nterms > 0) y = fmaf(w0 * dots[0], __ldg(&g_v[0 * P + col]), y);
            if (nterms > 1) y = fmaf(w1 * dots[1], __ldg(&g_v[1 * P + col]), y);
            if (nterms > 2) y = fmaf(w2 * dots[2], __ldg(&g_v[2 * P + col]), y);
            float ho = h_sm[col];
            hn_val = f_p(KAPPA * ho + ho * y);
            g_h[col] = hn_val;
            // publish dot partials of new h (skip after last iteration)
            if (nterms > 0 && it < N_ITER - 1) {
                for (int s = 0; s < nterms; ++s) {
                    float w = hn_val * __ldg(&g_u[s * P + col]);
#pragma unroll
                    for (int off = 16; off; off >>= 1)
                        w += __shfl_xor_sync(0xFFFFFFFFu, w, off);
                    if (lane == 0) psm[s][wid] = w;
                }
            }
        }
        if (nterms > 0 && it < N_ITER - 1) {
            __syncthreads();
            if (tid == 0)
                for (int s = 0; s < nterms; ++s)
                    g_dotpart[s * NBLK + b] = psm[s][0] + psm[s][1];
        }
        grid_barrier();
    }

    // ---- epilogue: loss partial, store u/v, block 0 finalizes ----
    if (tid < CPB) {
        int col = cb0 + tid;
        float p = x[t * NX + (col >> 6)] * gin[t * NG + (col & (NG - 1))];
        float h = hn_val;
        if (t < 3) {
            g_u[t * P + col] = p + h;
            g_v[t * P + col] = p - h;
        }
        float a = fabsf(p - h);
#pragma unroll
        for (int off = 16; off; off >>= 1)
            a += __shfl_xor_sync(0xFFFFFFFFu, a, off);
        if (lane == 0) psm[0][wid] = a;
    }
    __syncthreads();
    if (tid == 0) g_dotpart[b] = psm[0][0] + psm[0][1];
    grid_barrier();

    if (b == 0) {
        if (tid < NBLK) {
            float a = __ldcg(&g_dotpart[tid]);
#pragma unroll
            for (int off = 16; off; off >>= 1)
                a += __shfl_xor_sync(0xFFFFFFFFu, a, off);
            if (lane == 0) dsum[0][wid] = a;
        }
        __syncthreads();
        if (tid == 0) {
            float L = (t == 0 ? 0.f : g_loss) +
                      (((dsum[0][0] + dsum[0][1]) + dsum[0][2]) + dsum[0][3]);
            g_loss = L;
            *out = L;
        }
    }
}

extern "C" void kernel_launch(void* const* d_in, const int* in_sizes, int n_in,
                              void* d_out, int out_size) {
    const float* x = (const float*)d_in[0];   // [4,128]
    const float* g = (const float*)d_in[1];   // [4,64]
    const float* M = (const float*)d_in[2];   // [8192,8192]
    float* out = (float*)d_out;
    (void)in_sizes; (void)n_in; (void)out_size;

    k_convert<<<(int)((size_t)P * P / 8 / 256), 256>>>(M);

    for (int t = 0; t < T_STEPS; ++t) {
        float lam_pow = 1.0f;
        for (int i = 0; i < t; ++i) lam_pow *= LAMDA;
        float w[3] = {0.0f, 0.0f, 0.0f};
        for (int s = 0; s < t; ++s) {
            float lp = 1.0f;
            for (int i = 0; i < t - 1 - s; ++i) lp *= LAMDA;
            w[s] = YITA * lp;
        }
        k_attractor<<<NBLK, NTHR>>>(x, g, out, t, lam_pow, w[0], w[1], w[2]);
    }
}